// round 1
// baseline (speedup 1.0000x reference)
#include <cuda_runtime.h>
#include <cuda_bf16.h>
#include <math.h>

// ---------------- static problem shapes ----------------
#define BB    8
#define HH    56
#define WW    56
#define NN    (HH*WW)        // 3136
#define CC    256
#define NHEAD 8
#define CH    32
#define BN_TOT (BB*NN)       // 25088
#define QKVW  768
#define MH    1024

// ---------------- scratch (device globals; no allocation allowed) ----------------
__device__ float g_x1 [BN_TOT*CC];   // x after CPE residual
__device__ float g_cur[BN_TOT*CC];   // LN output (reused for LN1 and LN2)
__device__ float g_qkv[BN_TOT*QKVW]; // qkv projection
__device__ float g_att[BN_TOT*CC];   // gated attention pre-proj
__device__ float g_x2 [BN_TOT*CC];   // x after attention residual
__device__ float g_hid[BN_TOT*MH];   // MLP hidden
__device__ float g_kmax[BB*NHEAD*CH];
__device__ float g_ksum[BB*NHEAD*CH];
__device__ float g_kv  [BB*NHEAD*CH*CH];
__device__ float g_da  [BB*CC];

// ---------------- kernel 1: CPE depthwise 3x3 + residual, fused with LN1 ----------------
__global__ void cpe_ln1_kernel(const float* __restrict__ x,
                               const float* __restrict__ cpe_w,
                               const float* __restrict__ cpe_b,
                               const float* __restrict__ ln_g,
                               const float* __restrict__ ln_b) {
    int bn = blockIdx.x;
    int b  = bn / NN;
    int n  = bn % NN;
    int hh = n / WW, ww = n % WW;
    int c  = threadIdx.x;

    const float* xb = x + (size_t)b * NN * CC;
    float conv = cpe_b[c];
    const float* wc = cpe_w + c * 9;
    #pragma unroll
    for (int dy = -1; dy <= 1; dy++) {
        int y = hh + dy;
        if ((unsigned)y >= HH) continue;
        #pragma unroll
        for (int dx = -1; dx <= 1; dx++) {
            int xw = ww + dx;
            if ((unsigned)xw >= WW) continue;
            conv += xb[((size_t)(y * WW + xw)) * CC + c] * wc[(dy + 1) * 3 + (dx + 1)];
        }
    }
    float v = xb[(size_t)n * CC + c] + conv;
    g_x1[(size_t)bn * CC + c] = v;

    // LayerNorm over C=256
    __shared__ float s1[CC];
    __shared__ float s2[CC];
    s1[c] = v;
    s2[c] = v * v;
    __syncthreads();
    for (int off = 128; off > 0; off >>= 1) {
        if (c < off) { s1[c] += s1[c + off]; s2[c] += s2[c + off]; }
        __syncthreads();
    }
    float mean = s1[0] * (1.0f / CC);
    float var  = s2[0] * (1.0f / CC) - mean * mean;
    float inv  = rsqrtf(var + 1e-5f);
    g_cur[(size_t)bn * CC + c] = (v - mean) * inv * ln_g[c] + ln_b[c];
}

// ---------------- kernel: LN2 (no conv) ----------------
__global__ void ln2_kernel(const float* __restrict__ ln_g,
                           const float* __restrict__ ln_b) {
    int bn = blockIdx.x;
    int c  = threadIdx.x;
    float v = g_x2[(size_t)bn * CC + c];
    __shared__ float s1[CC];
    __shared__ float s2[CC];
    s1[c] = v;
    s2[c] = v * v;
    __syncthreads();
    for (int off = 128; off > 0; off >>= 1) {
        if (c < off) { s1[c] += s1[c + off]; s2[c] += s2[c + off]; }
        __syncthreads();
    }
    float mean = s1[0] * (1.0f / CC);
    float var  = s2[0] * (1.0f / CC) - mean * mean;
    float inv  = rsqrtf(var + 1e-5f);
    g_cur[(size_t)bn * CC + c] = (v - mean) * inv * ln_g[c] + ln_b[c];
}

// ---------------- tiled SGEMM 128x128x8, 8x8 per thread ----------------
// C[M,Nc] = A[M,K] @ B[K,Nc]   (all row-major, M%128==0, Nc%128==0, K%8==0)
// EPI 0: none; EPI 1: += bias[col] + res[row*Nc+col]; EPI 2: gelu(acc + bias[col])
template <int EPI>
__global__ __launch_bounds__(256)
void sgemm128(const float* __restrict__ A, const float* __restrict__ B,
              float* __restrict__ C, int M, int Nc, int K,
              const float* __restrict__ bias, const float* __restrict__ res) {
    __shared__ float As[8][128];
    __shared__ float Bs[8][128];

    const int tid = threadIdx.x;
    const int tr  = tid / 16;        // 0..15
    const int tc  = tid % 16;        // 0..15
    const int bx  = blockIdx.x;      // col block
    const int by  = blockIdx.y;      // row block

    const float* Ab = A + (size_t)by * 128 * K;
    const float* Bb = B + (size_t)bx * 128;

    const int arow = tid / 2;
    const int acol = (tid % 2) * 4;
    const int brow = tid / 32;
    const int bcol = (tid % 32) * 4;

    float acc[8][8];
    #pragma unroll
    for (int i = 0; i < 8; i++)
        #pragma unroll
        for (int j = 0; j < 8; j++) acc[i][j] = 0.f;

    for (int k0 = 0; k0 < K; k0 += 8) {
        float4 av = *(const float4*)(Ab + (size_t)arow * K + k0 + acol);
        As[acol + 0][arow] = av.x;
        As[acol + 1][arow] = av.y;
        As[acol + 2][arow] = av.z;
        As[acol + 3][arow] = av.w;
        float4 bv = *(const float4*)(Bb + (size_t)(k0 + brow) * Nc + bcol);
        *(float4*)(&Bs[brow][bcol]) = bv;
        __syncthreads();

        #pragma unroll
        for (int k = 0; k < 8; k++) {
            float4 m0 = *(const float4*)(&As[k][tr * 8]);
            float4 m1 = *(const float4*)(&As[k][tr * 8 + 4]);
            float4 n0 = *(const float4*)(&Bs[k][tc * 8]);
            float4 n1 = *(const float4*)(&Bs[k][tc * 8 + 4]);
            float rm[8] = {m0.x, m0.y, m0.z, m0.w, m1.x, m1.y, m1.z, m1.w};
            float rn[8] = {n0.x, n0.y, n0.z, n0.w, n1.x, n1.y, n1.z, n1.w};
            #pragma unroll
            for (int i = 0; i < 8; i++)
                #pragma unroll
                for (int j = 0; j < 8; j++) acc[i][j] += rm[i] * rn[j];
        }
        __syncthreads();
    }

    #pragma unroll
    for (int i = 0; i < 8; i++) {
        int row = by * 128 + tr * 8 + i;
        float* Crow = C + (size_t)row * Nc + bx * 128 + tc * 8;
        const float* Rrow = (EPI == 1) ? (res + (size_t)row * Nc + bx * 128 + tc * 8) : nullptr;
        float out[8];
        #pragma unroll
        for (int j = 0; j < 8; j++) {
            float v = acc[i][j];
            if (EPI == 1) {
                v += bias[bx * 128 + tc * 8 + j] + Rrow[j];
            } else if (EPI == 2) {
                v += bias[bx * 128 + tc * 8 + j];
                v = 0.5f * v * (1.0f + erff(v * 0.70710678118654752f));
            }
            out[j] = v;
        }
        *(float4*)(Crow)     = make_float4(out[0], out[1], out[2], out[3]);
        *(float4*)(Crow + 4) = make_float4(out[4], out[5], out[6], out[7]);
    }
}

// ---------------- kernel: per-(b,head,ch) softmax stats over tokens ----------------
__global__ void ksm_stats_kernel() {
    int bh   = blockIdx.x;          // 0..63
    int b    = bh / NHEAD;
    int head = bh % NHEAD;
    int lane = threadIdx.x & 31;    // ch
    int seg  = threadIdx.x >> 5;    // 0..7

    const float* base = g_qkv + (size_t)b * NN * QKVW + CC + head * CH + lane;

    float mx = -1e30f;
    for (int n = seg; n < NN; n += 8)
        mx = fmaxf(mx, base[(size_t)n * QKVW]);

    __shared__ float sm[8][32];
    sm[seg][lane] = mx;
    __syncthreads();
    if (seg == 0) {
        float m = sm[0][lane];
        #pragma unroll
        for (int i = 1; i < 8; i++) m = fmaxf(m, sm[i][lane]);
        sm[0][lane] = m;
    }
    __syncthreads();
    mx = sm[0][lane];
    __syncthreads();

    float s = 0.f;
    for (int n = seg; n < NN; n += 8)
        s += expf(base[(size_t)n * QKVW] - mx);

    sm[seg][lane] = s;
    __syncthreads();
    if (seg == 0) {
        float t = sm[0][lane];
        #pragma unroll
        for (int i = 1; i < 8; i++) t += sm[i][lane];
        g_kmax[bh * CH + lane] = mx;
        g_ksum[bh * CH + lane] = t;
    }
}

// ---------------- kernel: kv[b,h,32,32] = softmax(k)^T @ v ----------------
__global__ void kv_kernel() {
    int bh   = blockIdx.x;
    int b    = bh / NHEAD;
    int head = bh % NHEAD;
    int tid  = threadIdx.x;          // 1024
    int i    = tid >> 5;             // k-index
    int j    = tid & 31;             // v-index

    __shared__ float kt[32][33];
    __shared__ float vt[32][33];

    float kmax = g_kmax[bh * CH + i];  // per-column max used at load stage (below)
    float acc = 0.f;

    const float* qb = g_qkv + (size_t)b * NN * QKVW;
    int r = tid >> 5, c = tid & 31;
    float kmx_c = g_kmax[bh * CH + c];

    for (int t0 = 0; t0 < NN; t0 += 32) {
        const float* row = qb + (size_t)(t0 + r) * QKVW + head * CH + c;
        kt[r][c] = expf(row[CC]      - kmx_c);   // k at col 256+...
        vt[r][c] = row[2 * CC];                  // v at col 512+...
        __syncthreads();
        #pragma unroll
        for (int nn = 0; nn < 32; nn++)
            acc += kt[nn][i] * vt[nn][j];
        __syncthreads();
    }
    (void)kmax;
    g_kv[((size_t)bh * CH + i) * CH + j] = acc / g_ksum[bh * CH + i];
}

// ---------------- kernel: domain gating MLP + head softmax ----------------
__global__ void da_kernel(const float* __restrict__ dl,
                          const float* __restrict__ w1, const float* __restrict__ b1,
                          const float* __restrict__ w2, const float* __restrict__ b2) {
    __shared__ float hid[128];
    __shared__ float outb[BB * CC];   // 8KB
    int t = threadIdx.x;

    for (int b = 0; b < BB; b++) {
        if (t < 128) {
            float a = b1[t];
            #pragma unroll
            for (int k = 0; k < 4; k++) a += dl[b * 4 + k] * w1[k * 128 + t];
            hid[t] = fmaxf(a, 0.f);
        }
        __syncthreads();
        float o = b2[t];
        for (int i = 0; i < 128; i++) o += hid[i] * w2[i * CC + t];
        outb[b * CC + t] = o;
        __syncthreads();
    }

    int b  = t >> 5;
    int ch = t & 31;
    float m = -1e30f;
    #pragma unroll
    for (int hd = 0; hd < NHEAD; hd++)
        m = fmaxf(m, outb[b * CC + hd * CH + ch]);
    float e[NHEAD], s = 0.f;
    #pragma unroll
    for (int hd = 0; hd < NHEAD; hd++) {
        e[hd] = expf(outb[b * CC + hd * CH + ch] - m);
        s += e[hd];
    }
    float inv = 1.0f / s;
    #pragma unroll
    for (int hd = 0; hd < NHEAD; hd++)
        g_da[b * CC + hd * CH + ch] = e[hd] * inv;
}

// ---------------- kernel: factor-att + conv-RPE + gating -> g_att ----------------
__global__ void attn_build_kernel(const float* __restrict__ w3, const float* __restrict__ b3,
                                  const float* __restrict__ w5, const float* __restrict__ b5,
                                  const float* __restrict__ w7, const float* __restrict__ b7) {
    int bn = blockIdx.x;
    int b  = bn / NN;
    int n  = bn % NN;
    int hh = n / WW, ww = n % WW;
    int c  = threadIdx.x;
    int head = c >> 5;
    int ch   = c & 31;

    __shared__ float qrow[CC];
    const float* qkvrow = g_qkv + (size_t)bn * QKVW;
    qrow[c] = qkvrow[c];
    __syncthreads();

    // factor attention: scale * q @ kv
    const float* kvp = g_kv + ((size_t)(b * NHEAD + head) * CH) * CH + ch;
    const float* qh  = &qrow[head * CH];
    float fa = 0.f;
    #pragma unroll
    for (int k2 = 0; k2 < CH; k2++)
        fa += qh[k2] * kvp[k2 * CH];
    fa *= 0.17677669529663687f;   // 1/sqrt(32)

    // conv relative position encoding on v (channel c = head*32+ch)
    int ksz;
    const float* w;
    float cv;
    if (c < 64)       { ksz = 3; w = w3 + c * 9;          cv = b3[c]; }
    else if (c < 160) { ksz = 5; w = w5 + (c - 64) * 25;  cv = b5[c - 64]; }
    else              { ksz = 7; w = w7 + (c - 160) * 49; cv = b7[c - 160]; }
    int rad = ksz >> 1;
    const float* vb = g_qkv + (size_t)b * NN * QKVW + 2 * CC + c;
    for (int dy = -rad; dy <= rad; dy++) {
        int y = hh + dy;
        if ((unsigned)y >= HH) continue;
        for (int dx = -rad; dx <= rad; dx++) {
            int xw = ww + dx;
            if ((unsigned)xw >= WW) continue;
            cv += vb[(size_t)(y * WW + xw) * QKVW] * w[(dy + rad) * ksz + (dx + rad)];
        }
    }

    float q  = qrow[c];
    float da = g_da[b * CC + c];
    g_att[(size_t)bn * CC + c] = da * (fa + q * cv);
}

// ---------------- launch ----------------
extern "C" void kernel_launch(void* const* d_in, const int* in_sizes, int n_in,
                              void* d_out, int out_size) {
    const float* x      = (const float*)d_in[0];
    const float* dl     = (const float*)d_in[1];
    const float* cpe_w  = (const float*)d_in[2];
    const float* cpe_b  = (const float*)d_in[3];
    const float* ln1_g  = (const float*)d_in[4];   // domain d=0 -> first row
    const float* ln1_b  = (const float*)d_in[5];
    const float* qkv_w  = (const float*)d_in[6];
    const float* proj_w = (const float*)d_in[7];
    const float* proj_b = (const float*)d_in[8];
    const float* dl_w1  = (const float*)d_in[9];
    const float* dl_b1  = (const float*)d_in[10];
    const float* dl_w2  = (const float*)d_in[11];
    const float* dl_b2  = (const float*)d_in[12];
    const float* w3     = (const float*)d_in[13];
    const float* b3     = (const float*)d_in[14];
    const float* w5     = (const float*)d_in[15];
    const float* b5     = (const float*)d_in[16];
    const float* w7     = (const float*)d_in[17];
    const float* b7     = (const float*)d_in[18];
    const float* ln2_g  = (const float*)d_in[19];
    const float* ln2_b  = (const float*)d_in[20];
    const float* fc1_w  = (const float*)d_in[21];
    const float* fc1_b  = (const float*)d_in[22];
    const float* fc2_w  = (const float*)d_in[23];
    const float* fc2_b  = (const float*)d_in[24];
    float* out = (float*)d_out;

    float *p_x1, *p_cur, *p_qkv, *p_att, *p_x2, *p_hid;
    cudaGetSymbolAddress((void**)&p_x1,  g_x1);
    cudaGetSymbolAddress((void**)&p_cur, g_cur);
    cudaGetSymbolAddress((void**)&p_qkv, g_qkv);
    cudaGetSymbolAddress((void**)&p_att, g_att);
    cudaGetSymbolAddress((void**)&p_x2,  g_x2);
    cudaGetSymbolAddress((void**)&p_hid, g_hid);

    // 1. CPE + residual + LN1
    cpe_ln1_kernel<<<BN_TOT, CC>>>(x, cpe_w, cpe_b, ln1_g, ln1_b);

    // 2. qkv = cur @ qkv_w
    sgemm128<0><<<dim3(QKVW / 128, BN_TOT / 128), 256>>>(
        p_cur, qkv_w, p_qkv, BN_TOT, QKVW, CC, nullptr, nullptr);

    // 3. k softmax stats + 4. kv einsum
    ksm_stats_kernel<<<BB * NHEAD, 256>>>();
    kv_kernel<<<BB * NHEAD, 1024>>>();

    // 5. domain gating
    da_kernel<<<1, 256>>>(dl, dl_w1, dl_b1, dl_w2, dl_b2);

    // 6. gated attention build (factor att + crpe)
    attn_build_kernel<<<BN_TOT, CC>>>(w3, b3, w5, b5, w7, b7);

    // 7. x2 = x1 + att @ proj_w + proj_b
    sgemm128<1><<<dim3(CC / 128, BN_TOT / 128), 256>>>(
        p_att, proj_w, p_x2, BN_TOT, CC, CC, proj_b, p_x1);

    // 8. LN2
    ln2_kernel<<<BN_TOT, CC>>>(ln2_g, ln2_b);

    // 9. hid = gelu(cur @ fc1_w + fc1_b)
    sgemm128<2><<<dim3(MH / 128, BN_TOT / 128), 256>>>(
        p_cur, fc1_w, p_hid, BN_TOT, MH, CC, fc1_b, nullptr);

    // 10. out = x2 + hid @ fc2_w + fc2_b
    sgemm128<1><<<dim3(CC / 128, BN_TOT / 128), 256>>>(
        p_hid, fc2_w, out, BN_TOT, CC, MH, fc2_b, p_x2);
}

// round 3
// speedup vs baseline: 2.0192x; 2.0192x over previous
#include <cuda_runtime.h>
#include <stdint.h>
#include <math.h>

// ---------------- static problem shapes ----------------
#define BB    8
#define HH    56
#define WW    56
#define NN    (HH*WW)        // 3136
#define CC    256
#define NHEAD 8
#define CH    32
#define BN_TOT (BB*NN)       // 25088
#define QKVW  768
#define MH    1024

// ---------------- scratch (device globals) ----------------
__device__ float g_x1 [BN_TOT*CC];
__device__ float g_cur[BN_TOT*CC];
__device__ float g_qkv[BN_TOT*QKVW];
__device__ float g_att[BN_TOT*CC];
__device__ float g_x2 [BN_TOT*CC];
__device__ float g_hid[BN_TOT*MH];
__device__ float g_kv  [64*CH*CH];
__device__ float g_da  [BB*CC];
__device__ float g_kvp [8*64*CH*CH];
__device__ float g_ksp [8*64*CH];
__device__ float g_wt  [786432];       // tf32-rounded weights: qkv|proj|fc1|fc2

// ---------------- helpers ----------------
__device__ __forceinline__ uint32_t smem_u32(const void* p){
    uint32_t a; asm("{.reg .u64 t; cvta.to.shared.u64 t, %1; cvt.u32.u64 %0, t;}":"=r"(a):"l"(p)); return a;
}
__device__ __forceinline__ float tf32r(float x){
    uint32_t r; asm("cvt.rna.tf32.f32 %0, %1;":"=r"(r):"f"(x)); return __uint_as_float(r);
}
__device__ __forceinline__ void cp_async16(uint32_t dst, const void* src){
    asm volatile("cp.async.ca.shared.global [%0], [%1], 16;"::"r"(dst),"l"(src):"memory");
}
__device__ __forceinline__ void cp_commit(){ asm volatile("cp.async.commit_group;":::"memory"); }
template<int N> __device__ __forceinline__ void cp_wait(){ asm volatile("cp.async.wait_group %0;"::"n"(N):"memory"); }

__device__ __forceinline__ void mma_tf32(float* d, const uint32_t* a, const uint32_t* b){
    asm volatile(
        "mma.sync.aligned.m16n8k8.row.col.f32.tf32.tf32.f32 "
        "{%0,%1,%2,%3}, {%4,%5,%6,%7}, {%8,%9}, {%0,%1,%2,%3};"
        : "+f"(d[0]),"+f"(d[1]),"+f"(d[2]),"+f"(d[3])
        : "r"(a[0]),"r"(a[1]),"r"(a[2]),"r"(a[3]),"r"(b[0]),"r"(b[1]));
}

// ---------------- round weights to tf32 (one-time-ish, cheap) ----------------
__global__ void round_kernel(const float* __restrict__ src, float* __restrict__ dst, int n){
    int i = (blockIdx.x * blockDim.x + threadIdx.x) * 4;
    if (i < n) {
        float4 v = *(const float4*)(src + i);
        v.x = tf32r(v.x); v.y = tf32r(v.y); v.z = tf32r(v.z); v.w = tf32r(v.w);
        *(float4*)(dst + i) = v;
    }
}

// ---------------- kernel: CPE depthwise 3x3 + residual, fused with LN1 ----------------
__global__ void cpe_ln1_kernel(const float* __restrict__ x,
                               const float* __restrict__ cpe_w,
                               const float* __restrict__ cpe_b,
                               const float* __restrict__ ln_g,
                               const float* __restrict__ ln_b) {
    int bn = blockIdx.x;
    int b  = bn / NN;
    int n  = bn % NN;
    int hh = n / WW, ww = n % WW;
    int c  = threadIdx.x;

    const float* xb = x + (size_t)b * NN * CC;
    float conv = cpe_b[c];
    const float* wc = cpe_w + c * 9;
    #pragma unroll
    for (int dy = -1; dy <= 1; dy++) {
        int y = hh + dy;
        if ((unsigned)y >= HH) continue;
        #pragma unroll
        for (int dx = -1; dx <= 1; dx++) {
            int xw = ww + dx;
            if ((unsigned)xw >= WW) continue;
            conv += xb[((size_t)(y * WW + xw)) * CC + c] * wc[(dy + 1) * 3 + (dx + 1)];
        }
    }
    float v = xb[(size_t)n * CC + c] + conv;
    g_x1[(size_t)bn * CC + c] = v;

    __shared__ float s1[CC];
    __shared__ float s2[CC];
    s1[c] = v;
    s2[c] = v * v;
    __syncthreads();
    for (int off = 128; off > 0; off >>= 1) {
        if (c < off) { s1[c] += s1[c + off]; s2[c] += s2[c + off]; }
        __syncthreads();
    }
    float mean = s1[0] * (1.0f / CC);
    float var  = s2[0] * (1.0f / CC) - mean * mean;
    float inv  = rsqrtf(var + 1e-5f);
    g_cur[(size_t)bn * CC + c] = tf32r((v - mean) * inv * ln_g[c] + ln_b[c]);
}

// ---------------- LN2 ----------------
__global__ void ln2_kernel(const float* __restrict__ ln_g,
                           const float* __restrict__ ln_b) {
    int bn = blockIdx.x;
    int c  = threadIdx.x;
    float v = g_x2[(size_t)bn * CC + c];
    __shared__ float s1[CC];
    __shared__ float s2[CC];
    s1[c] = v;
    s2[c] = v * v;
    __syncthreads();
    for (int off = 128; off > 0; off >>= 1) {
        if (c < off) { s1[c] += s1[c + off]; s2[c] += s2[c + off]; }
        __syncthreads();
    }
    float mean = s1[0] * (1.0f / CC);
    float var  = s2[0] * (1.0f / CC) - mean * mean;
    float inv  = rsqrtf(var + 1e-5f);
    g_cur[(size_t)bn * CC + c] = tf32r((v - mean) * inv * ln_g[c] + ln_b[c]);
}

// ---------------- tensor-core tf32 GEMM via mma.sync ----------------
// C[M,Nc] = A[M,K] @ B[K,Nc]; A,B pre-rounded to tf32 values.
// Block 128x128, BK=32, 8 warps (2 m x 4 n), warp tile 64x32.
// EPI 0: none; EPI 1: += bias[col]+res; EPI 2: tf32r(gelu(acc+bias[col]))
#define AST 36
#define BST 136
#define GSM ((128*AST + 32*BST) * 2 * 4)   // 71680 bytes
template <int EPI>
__global__ __launch_bounds__(256)
void gemm_mma(const float* __restrict__ A, const float* __restrict__ B,
              float* __restrict__ C, int M, int Nc, int K,
              const float* __restrict__ bias, const float* __restrict__ res) {
    extern __shared__ float sm[];
    float* As[2] = { sm, sm + 128*AST + 32*BST };
    float* Bs[2] = { sm + 128*AST, sm + 2*128*AST + 32*BST };
    uint32_t asb[2] = { smem_u32(As[0]), smem_u32(As[1]) };
    uint32_t bsb[2] = { smem_u32(Bs[0]), smem_u32(Bs[1]) };

    const int tid  = threadIdx.x;
    const int lane = tid & 31;
    const int w    = tid >> 5;
    const int wm   = w & 1;          // 0..1
    const int wn   = w >> 1;         // 0..3
    const int g    = lane >> 2;      // 0..7
    const int qt   = lane & 3;       // 0..3

    const int bx = blockIdx.x, by = blockIdx.y;
    const float* Ab = A + (size_t)by * 128 * K;
    const float* Bb = B + (size_t)bx * 128;

    // cp.async source/dest mapping
    const int a_row = tid >> 1;            // 0..127
    const int a_kc  = (tid & 1) << 2;      // 0 or 4 (two 16B chunks per row half? -> 8 floats per thread-pair)
    // A tile is 128 rows x 32 floats = 8 chunks/row; map: idx = tid + 256*r, row=idx/8, kq=idx%8
    const int b_kr  = tid >> 5;            // reuse below

    float acc[4][4][4];
    #pragma unroll
    for (int i = 0; i < 4; i++)
        #pragma unroll
        for (int j = 0; j < 4; j++)
            #pragma unroll
            for (int q = 0; q < 4; q++) acc[i][j][q] = 0.f;

    const int S = K >> 5;

    auto load_stage = [&](int s, int buf) {
        const float* Ac = Ab + (s << 5);
        const float* Bc = Bb + (size_t)(s << 5) * Nc;
        #pragma unroll
        for (int r = 0; r < 4; r++) {
            int idx = tid + (r << 8);
            int row = idx >> 3, kq = (idx & 7) << 2;
            cp_async16(asb[buf] + (uint32_t)(row * AST + kq) * 4, Ac + (size_t)row * K + kq);
        }
        #pragma unroll
        for (int r = 0; r < 4; r++) {
            int idx = tid + (r << 8);
            int kr = idx >> 5, nq = (idx & 31) << 2;
            cp_async16(bsb[buf] + (uint32_t)(kr * BST + nq) * 4, Bc + (size_t)kr * Nc + nq);
        }
        cp_commit();
    };

    load_stage(0, 0);

    for (int s = 0; s < S; s++) {
        int buf = s & 1;
        if (s + 1 < S) { load_stage(s + 1, buf ^ 1); cp_wait<1>(); }
        else           { cp_wait<0>(); }
        __syncthreads();

        const float* Ap = As[buf];
        const float* Bp = Bs[buf];
        #pragma unroll
        for (int ks = 0; ks < 4; ks++) {
            int kk = ks << 3;
            uint32_t af[4][4], bf[4][2];
            #pragma unroll
            for (int mt = 0; mt < 4; mt++) {
                int m0 = wm * 64 + mt * 16;
                const float* base = Ap + (m0 + g) * AST + kk + qt;
                af[mt][0] = __float_as_uint(base[0]);
                af[mt][1] = __float_as_uint(base[8 * AST]);
                af[mt][2] = __float_as_uint(base[4]);
                af[mt][3] = __float_as_uint(base[8 * AST + 4]);
            }
            #pragma unroll
            for (int nt = 0; nt < 4; nt++) {
                int n0 = wn * 32 + nt * 8;
                const float* base = Bp + (kk + qt) * BST + n0 + g;
                bf[nt][0] = __float_as_uint(base[0]);
                bf[nt][1] = __float_as_uint(base[4 * BST]);
            }
            #pragma unroll
            for (int mt = 0; mt < 4; mt++)
                #pragma unroll
                for (int nt = 0; nt < 4; nt++)
                    mma_tf32(acc[mt][nt], af[mt], bf[nt]);
        }
        __syncthreads();
    }

    // epilogue
    #pragma unroll
    for (int mt = 0; mt < 4; mt++) {
        int row0 = by * 128 + wm * 64 + mt * 16 + g;
        #pragma unroll
        for (int nt = 0; nt < 4; nt++) {
            int col = bx * 128 + wn * 32 + nt * 8 + qt * 2;
            #pragma unroll
            for (int h = 0; h < 2; h++) {
                int row = row0 + h * 8;
                float v0 = acc[mt][nt][h * 2 + 0];
                float v1 = acc[mt][nt][h * 2 + 1];
                if (EPI == 1) {
                    v0 += bias[col]     + res[(size_t)row * Nc + col];
                    v1 += bias[col + 1] + res[(size_t)row * Nc + col + 1];
                } else if (EPI == 2) {
                    v0 += bias[col];
                    v1 += bias[col + 1];
                    v0 = tf32r(0.5f * v0 * (1.0f + erff(v0 * 0.70710678118654752f)));
                    v1 = tf32r(0.5f * v1 * (1.0f + erff(v1 * 0.70710678118654752f)));
                }
                *(float2*)(C + (size_t)row * Nc + col) = make_float2(v0, v1);
            }
        }
    }
}

// ---------------- kv partials ----------------
__global__ void kv_build_kernel() {
    int seg = blockIdx.x;
    int bh  = blockIdx.y;
    int b   = bh >> 3, head = bh & 7;
    int tid = threadIdx.x;
    int tt = tid >> 5, lane = tid & 31;
    int i = tid >> 3, jg = tid & 7, j = jg << 2;

    __shared__ __align__(16) float ks[8][32];
    __shared__ __align__(16) float vs[8][32];

    float a0 = 0.f, a1 = 0.f, a2 = 0.f, a3 = 0.f, ssum = 0.f;
    const float* qb = g_qkv + (size_t)b * NN * QKVW + head * CH;
    int n0 = seg * 392;

    for (int it = 0; it < 49; it++) {
        const float* row = qb + (size_t)(n0 + it * 8 + tt) * QKVW + lane;
        ks[tt][lane] = expf(row[CC]);
        vs[tt][lane] = row[2 * CC];
        __syncthreads();
        #pragma unroll
        for (int nn = 0; nn < 8; nn++) {
            float e = ks[nn][i];
            float4 v4 = *(const float4*)&vs[nn][j];
            a0 += e * v4.x; a1 += e * v4.y; a2 += e * v4.z; a3 += e * v4.w;
            if (jg == 0) ssum += e;
        }
        __syncthreads();
    }
    float* kvp = g_kvp + ((size_t)(seg * 64 + bh) * CH + i) * CH + j;
    kvp[0] = a0; kvp[1] = a1; kvp[2] = a2; kvp[3] = a3;
    if (jg == 0) g_ksp[(seg * 64 + bh) * CH + i] = ssum;
}

__global__ void kv_norm_kernel() {
    int bh = blockIdx.x;
    int t = threadIdx.x;
    int i = t >> 5, j = t & 31;
    float s = 0.f, kvv = 0.f;
    #pragma unroll
    for (int p = 0; p < 8; p++) {
        s   += g_ksp[(p * 64 + bh) * CH + i];
        kvv += g_kvp[((size_t)(p * 64 + bh) * CH + i) * CH + j];
    }
    g_kv[((size_t)bh * CH + i) * CH + j] = kvv / s;
}

// ---------------- domain gating MLP + head softmax ----------------
__global__ void da_kernel(const float* __restrict__ dl,
                          const float* __restrict__ w1, const float* __restrict__ b1,
                          const float* __restrict__ w2, const float* __restrict__ b2) {
    __shared__ float hid[128];
    __shared__ float outb[BB * CC];
    int t = threadIdx.x;

    for (int b = 0; b < BB; b++) {
        if (t < 128) {
            float a = b1[t];
            #pragma unroll
            for (int k = 0; k < 4; k++) a += dl[b * 4 + k] * w1[k * 128 + t];
            hid[t] = fmaxf(a, 0.f);
        }
        __syncthreads();
        float o = b2[t];
        for (int i = 0; i < 128; i++) o += hid[i] * w2[i * CC + t];
        outb[b * CC + t] = o;
        __syncthreads();
    }

    int b  = t >> 5;
    int ch = t & 31;
    float m = -1e30f;
    #pragma unroll
    for (int hd = 0; hd < NHEAD; hd++)
        m = fmaxf(m, outb[b * CC + hd * CH + ch]);
    float e[NHEAD], s = 0.f;
    #pragma unroll
    for (int hd = 0; hd < NHEAD; hd++) {
        e[hd] = expf(outb[b * CC + hd * CH + ch] - m);
        s += e[hd];
    }
    float inv = 1.0f / s;
    #pragma unroll
    for (int hd = 0; hd < NHEAD; hd++)
        g_da[b * CC + hd * CH + ch] = e[hd] * inv;
}

// ---------------- factor-att + conv-RPE + gating -> g_att ----------------
__global__ void attn_build_kernel(const float* __restrict__ w3, const float* __restrict__ b3,
                                  const float* __restrict__ w5, const float* __restrict__ b5,
                                  const float* __restrict__ w7, const float* __restrict__ b7) {
    int bn = blockIdx.x;
    int b  = bn / NN;
    int n  = bn % NN;
    int hh = n / WW, ww = n % WW;
    int c  = threadIdx.x;
    int head = c >> 5;
    int ch   = c & 31;

    __shared__ float qrow[CC];
    const float* qkvrow = g_qkv + (size_t)bn * QKVW;
    qrow[c] = qkvrow[c];
    __syncthreads();

    const float* kvp = g_kv + ((size_t)(b * NHEAD + head) * CH) * CH + ch;
    const float* qh  = &qrow[head * CH];
    float fa = 0.f;
    #pragma unroll
    for (int k2 = 0; k2 < CH; k2++)
        fa += qh[k2] * kvp[k2 * CH];
    fa *= 0.17677669529663687f;

    int ksz;
    const float* w;
    float cv;
    if (c < 64)       { ksz = 3; w = w3 + c * 9;          cv = b3[c]; }
    else if (c < 160) { ksz = 5; w = w5 + (c - 64) * 25;  cv = b5[c - 64]; }
    else              { ksz = 7; w = w7 + (c - 160) * 49; cv = b7[c - 160]; }
    int rad = ksz >> 1;
    const float* vb = g_qkv + (size_t)b * NN * QKVW + 2 * CC + c;
    for (int dy = -rad; dy <= rad; dy++) {
        int y = hh + dy;
        if ((unsigned)y >= HH) continue;
        for (int dx = -rad; dx <= rad; dx++) {
            int xw = ww + dx;
            if ((unsigned)xw >= WW) continue;
            cv += vb[(size_t)(y * WW + xw) * QKVW] * w[(dy + rad) * ksz + (dx + rad)];
        }
    }

    float q  = qrow[c];
    float da = g_da[b * CC + c];
    g_att[(size_t)bn * CC + c] = tf32r(da * (fa + q * cv));
}

// ---------------- launch ----------------
extern "C" void kernel_launch(void* const* d_in, const int* in_sizes, int n_in,
                              void* d_out, int out_size) {
    const float* x      = (const float*)d_in[0];
    const float* dl     = (const float*)d_in[1];
    const float* cpe_w  = (const float*)d_in[2];
    const float* cpe_b  = (const float*)d_in[3];
    const float* ln1_g  = (const float*)d_in[4];
    const float* ln1_b  = (const float*)d_in[5];
    const float* qkv_w  = (const float*)d_in[6];
    const float* proj_w = (const float*)d_in[7];
    const float* proj_b = (const float*)d_in[8];
    const float* dl_w1  = (const float*)d_in[9];
    const float* dl_b1  = (const float*)d_in[10];
    const float* dl_w2  = (const float*)d_in[11];
    const float* dl_b2  = (const float*)d_in[12];
    const float* w3     = (const float*)d_in[13];
    const float* b3     = (const float*)d_in[14];
    const float* w5     = (const float*)d_in[15];
    const float* b5     = (const float*)d_in[16];
    const float* w7     = (const float*)d_in[17];
    const float* b7     = (const float*)d_in[18];
    const float* ln2_g  = (const float*)d_in[19];
    const float* ln2_b  = (const float*)d_in[20];
    const float* fc1_w  = (const float*)d_in[21];
    const float* fc1_b  = (const float*)d_in[22];
    const float* fc2_w  = (const float*)d_in[23];
    const float* fc2_b  = (const float*)d_in[24];
    float* out = (float*)d_out;

    float *p_cur, *p_qkv, *p_att, *p_x1, *p_x2, *p_hid, *p_wt;
    cudaGetSymbolAddress((void**)&p_x1,  g_x1);
    cudaGetSymbolAddress((void**)&p_cur, g_cur);
    cudaGetSymbolAddress((void**)&p_qkv, g_qkv);
    cudaGetSymbolAddress((void**)&p_att, g_att);
    cudaGetSymbolAddress((void**)&p_x2,  g_x2);
    cudaGetSymbolAddress((void**)&p_hid, g_hid);
    cudaGetSymbolAddress((void**)&p_wt,  g_wt);

    float* qkvR = p_wt;             // [256,768]
    float* projR = p_wt + 196608;   // [256,256]
    float* fc1R  = p_wt + 262144;   // [256,1024]
    float* fc2R  = p_wt + 524288;   // [1024,256]

    cudaFuncSetAttribute(gemm_mma<0>, cudaFuncAttributeMaxDynamicSharedMemorySize, GSM);
    cudaFuncSetAttribute(gemm_mma<1>, cudaFuncAttributeMaxDynamicSharedMemorySize, GSM);
    cudaFuncSetAttribute(gemm_mma<2>, cudaFuncAttributeMaxDynamicSharedMemorySize, GSM);

    // 0. round weights to tf32 (keep [K,N] layout)
    round_kernel<<<192, 256>>>(qkv_w,  qkvR, 196608);
    round_kernel<<<64,  256>>>(proj_w, projR, 65536);
    round_kernel<<<256, 256>>>(fc1_w,  fc1R, 262144);
    round_kernel<<<256, 256>>>(fc2_w,  fc2R, 262144);

    // 1. CPE + residual + LN1 (writes tf32-rounded g_cur)
    cpe_ln1_kernel<<<BN_TOT, CC>>>(x, cpe_w, cpe_b, ln1_g, ln1_b);

    // 2. qkv = cur @ qkv_w
    gemm_mma<0><<<dim3(QKVW/128, BN_TOT/128), 256, GSM>>>(
        p_cur, qkvR, p_qkv, BN_TOT, QKVW, CC, nullptr, nullptr);

    // 3. kv
    kv_build_kernel<<<dim3(8, 64), 256>>>();
    kv_norm_kernel<<<64, 1024>>>();

    // 4. domain gating
    da_kernel<<<1, 256>>>(dl, dl_w1, dl_b1, dl_w2, dl_b2);

    // 5. attention build
    attn_build_kernel<<<BN_TOT, CC>>>(w3, b3, w5, b5, w7, b7);

    // 6. x2 = x1 + att @ proj_w + proj_b
    gemm_mma<1><<<dim3(CC/128, BN_TOT/128), 256, GSM>>>(
        p_att, projR, p_x2, BN_TOT, CC, CC, proj_b, p_x1);

    // 7. LN2
    ln2_kernel<<<BN_TOT, CC>>>(ln2_g, ln2_b);

    // 8. hid = gelu(cur @ fc1_w + fc1_b)  (tf32-rounded)
    gemm_mma<2><<<dim3(MH/128, BN_TOT/128), 256, GSM>>>(
        p_cur, fc1R, p_hid, BN_TOT, MH, CC, fc1_b, nullptr);

    // 9. out = x2 + hid @ fc2_w + fc2_b
    gemm_mma<1><<<dim3(CC/128, BN_TOT/128), 256, GSM>>>(
        p_hid, fc2R, out, BN_TOT, CC, MH, fc2_b, p_x2);
}

// round 4
// speedup vs baseline: 2.7052x; 1.3398x over previous
#include <cuda_runtime.h>
#include <cuda_fp16.h>
#include <stdint.h>
#include <math.h>

// ---------------- static problem shapes ----------------
#define BB    8
#define HH    56
#define WW    56
#define NN    (HH*WW)        // 3136
#define CC    256
#define NHEAD 8
#define CH    32
#define BN_TOT (BB*NN)       // 25088
#define QKVW  768
#define MH    1024

// ---------------- scratch (device globals) ----------------
__device__ float  g_x1 [BN_TOT*CC];
__device__ float  g_x2 [BN_TOT*CC];
__device__ float  g_qkv[BN_TOT*QKVW];
__device__ __align__(16) __half g_curh[BN_TOT*CC];
__device__ __align__(16) __half g_atth[BN_TOT*CC];
__device__ __align__(16) __half g_hidh[BN_TOT*MH];
__device__ __align__(16) __half g_wth [786432];     // qkv|proj|fc1|fc2 as half [K][N]
__device__ float  g_kv  [64*CH*CH];
__device__ float  g_da  [BB*CC];
__device__ float  g_kvp [8*64*CH*CH];
__device__ float  g_ksp [8*64*CH];

// ---------------- helpers ----------------
__device__ __forceinline__ uint32_t smem_u32(const void* p){
    uint32_t a; asm("{.reg .u64 t; cvta.to.shared.u64 t, %1; cvt.u32.u64 %0, t;}":"=r"(a):"l"(p)); return a;
}
__device__ __forceinline__ void cp_async16(uint32_t dst, const void* src){
    asm volatile("cp.async.ca.shared.global [%0], [%1], 16;"::"r"(dst),"l"(src):"memory");
}
__device__ __forceinline__ void cp_commit(){ asm volatile("cp.async.commit_group;":::"memory"); }
template<int N> __device__ __forceinline__ void cp_wait(){ asm volatile("cp.async.wait_group %0;"::"n"(N):"memory"); }

__device__ __forceinline__ void ldsm4(uint32_t* r, uint32_t addr){
    asm volatile("ldmatrix.sync.aligned.m8n8.x4.shared.b16 {%0,%1,%2,%3}, [%4];"
        :"=r"(r[0]),"=r"(r[1]),"=r"(r[2]),"=r"(r[3]):"r"(addr));
}
__device__ __forceinline__ void ldsm4t(uint32_t* r, uint32_t addr){
    asm volatile("ldmatrix.sync.aligned.m8n8.x4.trans.shared.b16 {%0,%1,%2,%3}, [%4];"
        :"=r"(r[0]),"=r"(r[1]),"=r"(r[2]),"=r"(r[3]):"r"(addr));
}
__device__ __forceinline__ void mma_f16(float* d, const uint32_t* a, const uint32_t* b){
    asm volatile(
        "mma.sync.aligned.m16n8k16.row.col.f32.f16.f16.f32 "
        "{%0,%1,%2,%3}, {%4,%5,%6,%7}, {%8,%9}, {%0,%1,%2,%3};"
        : "+f"(d[0]),"+f"(d[1]),"+f"(d[2]),"+f"(d[3])
        : "r"(a[0]),"r"(a[1]),"r"(a[2]),"r"(a[3]),"r"(b[0]),"r"(b[1]));
}

// swizzled byte offsets inside smem stages
// A stage: 128 rows x 64 halves (128B = 8 chunks of 16B)
__device__ __forceinline__ uint32_t aoff(int r, int q){
    return (uint32_t)((r << 7) + (((q ^ (r & 7)) & 7) << 4));
}
// B stage: 64 k-rows x 128 halves (256B = 16 chunks)
__device__ __forceinline__ uint32_t boff(int k, int c){
    return (uint32_t)((k << 8) + ((((c & 8) | ((c & 7) ^ (k & 7)))) << 4));
}

// ---------------- convert fp32 -> half ----------------
__global__ void f2h_kernel(const float* __restrict__ src, __half* __restrict__ dst, int n){
    int i = (blockIdx.x * blockDim.x + threadIdx.x) * 4;
    if (i < n) {
        float4 v = *(const float4*)(src + i);
        __half2 h0 = __floats2half2_rn(v.x, v.y);
        __half2 h1 = __floats2half2_rn(v.z, v.w);
        *(uint2*)(dst + i) = make_uint2(*(uint32_t*)&h0, *(uint32_t*)&h1);
    }
}

// ---------------- CPE depthwise 3x3 + residual + LN1 (half out) ----------------
__global__ void cpe_ln1_kernel(const float* __restrict__ x,
                               const float* __restrict__ cpe_w,
                               const float* __restrict__ cpe_b,
                               const float* __restrict__ ln_g,
                               const float* __restrict__ ln_b) {
    int bn = blockIdx.x;
    int b  = bn / NN;
    int n  = bn % NN;
    int hh = n / WW, ww = n % WW;
    int c  = threadIdx.x;

    const float* xb = x + (size_t)b * NN * CC;
    float conv = cpe_b[c];
    const float* wc = cpe_w + c * 9;
    #pragma unroll
    for (int dy = -1; dy <= 1; dy++) {
        int y = hh + dy;
        if ((unsigned)y >= HH) continue;
        #pragma unroll
        for (int dx = -1; dx <= 1; dx++) {
            int xw = ww + dx;
            if ((unsigned)xw >= WW) continue;
            conv += xb[((size_t)(y * WW + xw)) * CC + c] * wc[(dy + 1) * 3 + (dx + 1)];
        }
    }
    float v = xb[(size_t)n * CC + c] + conv;
    g_x1[(size_t)bn * CC + c] = v;

    __shared__ float s1[CC];
    __shared__ float s2[CC];
    s1[c] = v;
    s2[c] = v * v;
    __syncthreads();
    for (int off = 128; off > 0; off >>= 1) {
        if (c < off) { s1[c] += s1[c + off]; s2[c] += s2[c + off]; }
        __syncthreads();
    }
    float mean = s1[0] * (1.0f / CC);
    float var  = s2[0] * (1.0f / CC) - mean * mean;
    float inv  = rsqrtf(var + 1e-5f);
    g_curh[(size_t)bn * CC + c] = __float2half((v - mean) * inv * ln_g[c] + ln_b[c]);
}

// ---------------- LN2 (half out) ----------------
__global__ void ln2_kernel(const float* __restrict__ ln_g,
                           const float* __restrict__ ln_b) {
    int bn = blockIdx.x;
    int c  = threadIdx.x;
    float v = g_x2[(size_t)bn * CC + c];
    __shared__ float s1[CC];
    __shared__ float s2[CC];
    s1[c] = v;
    s2[c] = v * v;
    __syncthreads();
    for (int off = 128; off > 0; off >>= 1) {
        if (c < off) { s1[c] += s1[c + off]; s2[c] += s2[c + off]; }
        __syncthreads();
    }
    float mean = s1[0] * (1.0f / CC);
    float var  = s2[0] * (1.0f / CC) - mean * mean;
    float inv  = rsqrtf(var + 1e-5f);
    g_curh[(size_t)bn * CC + c] = __float2half((v - mean) * inv * ln_g[c] + ln_b[c]);
}

// ---------------- fp16 tensor-core GEMM ----------------
// C[M,Nc] = A[M,K] @ B[K,Nc]; A,B half; acc fp32.
// Block 128x128, BK=64 halves, 3-stage cp.async ring, 8 warps (2m x 4n), warp 64x32.
// EPI 0: fp32 C raw; EPI 1: fp32 C = acc + bias[col] + res; EPI 2: half C = gelu(acc + bias[col])
#define ASTB 16384
#define BSTB 16384
#define STGB (ASTB + BSTB)
#define GSM  (3 * STGB)       // 98304
template <int EPI>
__global__ __launch_bounds__(256)
void gemm_h(const __half* __restrict__ A, const __half* __restrict__ B,
            void* __restrict__ Cv, int M, int Nc, int K,
            const float* __restrict__ bias, const float* __restrict__ res) {
    extern __shared__ char smc[];
    uint32_t sb = smem_u32(smc);
    const int tid  = threadIdx.x;
    const int lane = tid & 31;
    const int w    = tid >> 5;
    const int wm   = w & 1;
    const int wn   = w >> 1;
    const int g    = lane >> 2;
    const int qt   = lane & 3;
    const int sub  = lane >> 3;
    const int rin  = lane & 7;

    const __half* Ab = A + (size_t)blockIdx.y * 128 * K;
    const __half* Bb = B + (size_t)blockIdx.x * 128;
    const int S = K >> 6;

    auto load = [&](int s, int buf) {
        uint32_t ab  = sb + buf * STGB;
        uint32_t bbs = ab + ASTB;
        const __half* Ac = Ab + (s << 6);
        const __half* Bc = Bb + (size_t)(s << 6) * Nc;
        #pragma unroll
        for (int r2 = 0; r2 < 4; r2++) {
            int idx = tid + (r2 << 8);
            int row = idx >> 3, q = idx & 7;
            cp_async16(ab + aoff(row, q), Ac + (size_t)row * K + (q << 3));
        }
        #pragma unroll
        for (int r2 = 0; r2 < 4; r2++) {
            int idx = tid + (r2 << 8);
            int k = idx >> 4, c = idx & 15;
            cp_async16(bbs + boff(k, c), Bc + (size_t)k * Nc + (c << 3));
        }
        cp_commit();
    };

    float acc[4][4][4];
    #pragma unroll
    for (int i = 0; i < 4; i++)
        #pragma unroll
        for (int j = 0; j < 4; j++)
            #pragma unroll
            for (int q = 0; q < 4; q++) acc[i][j][q] = 0.f;

    load(0, 0);
    load(1, 1);

    for (int s = 0; s < S; s++) {
        int buf = s % 3;
        if (s + 1 < S) cp_wait<1>(); else cp_wait<0>();
        __syncthreads();
        if (s + 2 < S) load(s + 2, (s + 2) % 3);

        uint32_t ab  = sb + buf * STGB;
        uint32_t bbs = ab + ASTB;
        #pragma unroll
        for (int ks = 0; ks < 4; ks++) {
            uint32_t af[4][4];
            #pragma unroll
            for (int mt = 0; mt < 4; mt++) {
                int m = wm * 64 + mt * 16 + (sub & 1) * 8 + rin;
                int q = ks * 2 + (sub >> 1);
                ldsm4(af[mt], ab + aoff(m, q));
            }
            uint32_t bf[2][4];
            #pragma unroll
            for (int p = 0; p < 2; p++) {
                int k = ks * 16 + (sub & 1) * 8 + rin;
                int c = wn * 4 + p * 2 + (sub >> 1);
                ldsm4t(bf[p], bbs + boff(k, c));
            }
            #pragma unroll
            for (int mt = 0; mt < 4; mt++)
                #pragma unroll
                for (int nt = 0; nt < 4; nt++)
                    mma_f16(acc[mt][nt], af[mt], &bf[nt >> 1][(nt & 1) * 2]);
        }
        __syncthreads();
    }

    // epilogue
    #pragma unroll
    for (int mt = 0; mt < 4; mt++) {
        int row0 = blockIdx.y * 128 + wm * 64 + mt * 16 + g;
        #pragma unroll
        for (int nt = 0; nt < 4; nt++) {
            int col = blockIdx.x * 128 + wn * 32 + nt * 8 + qt * 2;
            #pragma unroll
            for (int h = 0; h < 2; h++) {
                int row = row0 + h * 8;
                float v0 = acc[mt][nt][h * 2 + 0];
                float v1 = acc[mt][nt][h * 2 + 1];
                if (EPI == 0) {
                    *(float2*)((float*)Cv + (size_t)row * Nc + col) = make_float2(v0, v1);
                } else if (EPI == 1) {
                    v0 += bias[col]     + res[(size_t)row * Nc + col];
                    v1 += bias[col + 1] + res[(size_t)row * Nc + col + 1];
                    *(float2*)((float*)Cv + (size_t)row * Nc + col) = make_float2(v0, v1);
                } else {
                    v0 += bias[col];
                    v1 += bias[col + 1];
                    v0 = 0.5f * v0 * (1.0f + erff(v0 * 0.70710678118654752f));
                    v1 = 0.5f * v1 * (1.0f + erff(v1 * 0.70710678118654752f));
                    __half2 hv = __floats2half2_rn(v0, v1);
                    *(__half2*)((__half*)Cv + (size_t)row * Nc + col) = hv;
                }
            }
        }
    }
}

// ---------------- kv partials ----------------
__global__ void kv_build_kernel() {
    int seg = blockIdx.x;
    int bh  = blockIdx.y;
    int b   = bh >> 3, head = bh & 7;
    int tid = threadIdx.x;
    int tt = tid >> 5, lane = tid & 31;
    int i = tid >> 3, jg = tid & 7, j = jg << 2;

    __shared__ __align__(16) float ks[8][32];
    __shared__ __align__(16) float vs[8][32];

    float a0 = 0.f, a1 = 0.f, a2 = 0.f, a3 = 0.f, ssum = 0.f;
    const float* qb = g_qkv + (size_t)b * NN * QKVW + head * CH;
    int n0 = seg * 392;

    for (int it = 0; it < 49; it++) {
        const float* row = qb + (size_t)(n0 + it * 8 + tt) * QKVW + lane;
        ks[tt][lane] = expf(row[CC]);
        vs[tt][lane] = row[2 * CC];
        __syncthreads();
        #pragma unroll
        for (int nn = 0; nn < 8; nn++) {
            float e = ks[nn][i];
            float4 v4 = *(const float4*)&vs[nn][j];
            a0 += e * v4.x; a1 += e * v4.y; a2 += e * v4.z; a3 += e * v4.w;
            if (jg == 0) ssum += e;
        }
        __syncthreads();
    }
    float* kvp = g_kvp + ((size_t)(seg * 64 + bh) * CH + i) * CH + j;
    kvp[0] = a0; kvp[1] = a1; kvp[2] = a2; kvp[3] = a3;
    if (jg == 0) g_ksp[(seg * 64 + bh) * CH + i] = ssum;
}

__global__ void kv_norm_kernel() {
    int bh = blockIdx.x;
    int t = threadIdx.x;
    int i = t >> 5, j = t & 31;
    float s = 0.f, kvv = 0.f;
    #pragma unroll
    for (int p = 0; p < 8; p++) {
        s   += g_ksp[(p * 64 + bh) * CH + i];
        kvv += g_kvp[((size_t)(p * 64 + bh) * CH + i) * CH + j];
    }
    g_kv[((size_t)bh * CH + i) * CH + j] = kvv / s;
}

// ---------------- domain gating MLP + head softmax ----------------
__global__ void da_kernel(const float* __restrict__ dl,
                          const float* __restrict__ w1, const float* __restrict__ b1,
                          const float* __restrict__ w2, const float* __restrict__ b2) {
    __shared__ float hid[128];
    __shared__ float outb[BB * CC];
    int t = threadIdx.x;

    for (int b = 0; b < BB; b++) {
        if (t < 128) {
            float a = b1[t];
            #pragma unroll
            for (int k = 0; k < 4; k++) a += dl[b * 4 + k] * w1[k * 128 + t];
            hid[t] = fmaxf(a, 0.f);
        }
        __syncthreads();
        float o = b2[t];
        for (int i = 0; i < 128; i++) o += hid[i] * w2[i * CC + t];
        outb[b * CC + t] = o;
        __syncthreads();
    }

    int b  = t >> 5;
    int ch = t & 31;
    float m = -1e30f;
    #pragma unroll
    for (int hd = 0; hd < NHEAD; hd++)
        m = fmaxf(m, outb[b * CC + hd * CH + ch]);
    float e[NHEAD], s = 0.f;
    #pragma unroll
    for (int hd = 0; hd < NHEAD; hd++) {
        e[hd] = expf(outb[b * CC + hd * CH + ch] - m);
        s += e[hd];
    }
    float inv = 1.0f / s;
    #pragma unroll
    for (int hd = 0; hd < NHEAD; hd++)
        g_da[b * CC + hd * CH + ch] = e[hd] * inv;
}

// ---------------- factor-att + conv-RPE + gating -> g_atth (half) ----------------
__global__ void attn_build_kernel(const float* __restrict__ w3, const float* __restrict__ b3,
                                  const float* __restrict__ w5, const float* __restrict__ b5,
                                  const float* __restrict__ w7, const float* __restrict__ b7) {
    int bn = blockIdx.x;
    int b  = bn / NN;
    int n  = bn % NN;
    int hh = n / WW, ww = n % WW;
    int c  = threadIdx.x;
    int head = c >> 5;
    int ch   = c & 31;

    __shared__ float qrow[CC];
    const float* qkvrow = g_qkv + (size_t)bn * QKVW;
    qrow[c] = qkvrow[c];
    __syncthreads();

    const float* kvp = g_kv + ((size_t)(b * NHEAD + head) * CH) * CH + ch;
    const float* qh  = &qrow[head * CH];
    float fa = 0.f;
    #pragma unroll
    for (int k2 = 0; k2 < CH; k2++)
        fa += qh[k2] * kvp[k2 * CH];
    fa *= 0.17677669529663687f;

    int ksz;
    const float* w;
    float cv;
    if (c < 64)       { ksz = 3; w = w3 + c * 9;          cv = b3[c]; }
    else if (c < 160) { ksz = 5; w = w5 + (c - 64) * 25;  cv = b5[c - 64]; }
    else              { ksz = 7; w = w7 + (c - 160) * 49; cv = b7[c - 160]; }
    int rad = ksz >> 1;
    const float* vb = g_qkv + (size_t)b * NN * QKVW + 2 * CC + c;
    for (int dy = -rad; dy <= rad; dy++) {
        int y = hh + dy;
        if ((unsigned)y >= HH) continue;
        for (int dx = -rad; dx <= rad; dx++) {
            int xw = ww + dx;
            if ((unsigned)xw >= WW) continue;
            cv += vb[(size_t)(y * WW + xw) * QKVW] * w[(dy + rad) * ksz + (dx + rad)];
        }
    }

    float q  = qrow[c];
    float da = g_da[b * CC + c];
    g_atth[(size_t)bn * CC + c] = __float2half(da * (fa + q * cv));
}

// ---------------- launch ----------------
extern "C" void kernel_launch(void* const* d_in, const int* in_sizes, int n_in,
                              void* d_out, int out_size) {
    const float* x      = (const float*)d_in[0];
    const float* dl     = (const float*)d_in[1];
    const float* cpe_w  = (const float*)d_in[2];
    const float* cpe_b  = (const float*)d_in[3];
    const float* ln1_g  = (const float*)d_in[4];
    const float* ln1_b  = (const float*)d_in[5];
    const float* qkv_w  = (const float*)d_in[6];
    const float* proj_w = (const float*)d_in[7];
    const float* proj_b = (const float*)d_in[8];
    const float* dl_w1  = (const float*)d_in[9];
    const float* dl_b1  = (const float*)d_in[10];
    const float* dl_w2  = (const float*)d_in[11];
    const float* dl_b2  = (const float*)d_in[12];
    const float* w3     = (const float*)d_in[13];
    const float* b3     = (const float*)d_in[14];
    const float* w5     = (const float*)d_in[15];
    const float* b5     = (const float*)d_in[16];
    const float* w7     = (const float*)d_in[17];
    const float* b7     = (const float*)d_in[18];
    const float* ln2_g  = (const float*)d_in[19];
    const float* ln2_b  = (const float*)d_in[20];
    const float* fc1_w  = (const float*)d_in[21];
    const float* fc1_b  = (const float*)d_in[22];
    const float* fc2_w  = (const float*)d_in[23];
    const float* fc2_b  = (const float*)d_in[24];
    float* out = (float*)d_out;

    float *p_x1, *p_x2, *p_qkv;
    __half *p_curh, *p_atth, *p_hidh, *p_wth;
    cudaGetSymbolAddress((void**)&p_x1,   g_x1);
    cudaGetSymbolAddress((void**)&p_x2,   g_x2);
    cudaGetSymbolAddress((void**)&p_qkv,  g_qkv);
    cudaGetSymbolAddress((void**)&p_curh, g_curh);
    cudaGetSymbolAddress((void**)&p_atth, g_atth);
    cudaGetSymbolAddress((void**)&p_hidh, g_hidh);
    cudaGetSymbolAddress((void**)&p_wth,  g_wth);

    __half* qkvH = p_wth;             // [256,768]
    __half* projH = p_wth + 196608;   // [256,256]
    __half* fc1H  = p_wth + 262144;   // [256,1024]
    __half* fc2H  = p_wth + 524288;   // [1024,256]

    cudaFuncSetAttribute(gemm_h<0>, cudaFuncAttributeMaxDynamicSharedMemorySize, GSM);
    cudaFuncSetAttribute(gemm_h<1>, cudaFuncAttributeMaxDynamicSharedMemorySize, GSM);
    cudaFuncSetAttribute(gemm_h<2>, cudaFuncAttributeMaxDynamicSharedMemorySize, GSM);

    // 0. weights fp32 -> half (keep [K,N] layout)
    f2h_kernel<<<192, 256>>>(qkv_w,  qkvH, 196608);
    f2h_kernel<<<64,  256>>>(proj_w, projH, 65536);
    f2h_kernel<<<256, 256>>>(fc1_w,  fc1H, 262144);
    f2h_kernel<<<256, 256>>>(fc2_w,  fc2H, 262144);

    // 1. CPE + residual + LN1 (half out)
    cpe_ln1_kernel<<<BN_TOT, CC>>>(x, cpe_w, cpe_b, ln1_g, ln1_b);

    // 2. qkv = cur @ qkv_w  -> fp32
    gemm_h<0><<<dim3(QKVW/128, BN_TOT/128), 256, GSM>>>(
        p_curh, qkvH, p_qkv, BN_TOT, QKVW, CC, nullptr, nullptr);

    // 3. kv
    kv_build_kernel<<<dim3(8, 64), 256>>>();
    kv_norm_kernel<<<64, 1024>>>();

    // 4. domain gating
    da_kernel<<<1, 256>>>(dl, dl_w1, dl_b1, dl_w2, dl_b2);

    // 5. attention build (half out)
    attn_build_kernel<<<BN_TOT, CC>>>(w3, b3, w5, b5, w7, b7);

    // 6. x2 = x1 + att @ proj_w + proj_b  -> fp32
    gemm_h<1><<<dim3(CC/128, BN_TOT/128), 256, GSM>>>(
        p_atth, projH, p_x2, BN_TOT, CC, CC, proj_b, p_x1);

    // 7. LN2 (half out)
    ln2_kernel<<<BN_TOT, CC>>>(ln2_g, ln2_b);

    // 8. hid = gelu(cur @ fc1_w + fc1_b) -> half
    gemm_h<2><<<dim3(MH/128, BN_TOT/128), 256, GSM>>>(
        p_curh, fc1H, p_hidh, BN_TOT, MH, CC, fc1_b, nullptr);

    // 9. out = x2 + hid @ fc2_w + fc2_b -> fp32
    gemm_h<1><<<dim3(CC/128, BN_TOT/128), 256, GSM>>>(
        p_hidh, fc2H, out, BN_TOT, CC, MH, fc2_b, p_x2);
}